// round 10
// baseline (speedup 1.0000x reference)
#include <cuda_runtime.h>
#include <math.h>

// Problem constants (fixed by setup_inputs)
#define BB   32
#define AA   3
#define HH   64
#define WW   64
#define CC   80
#define PRED_LAST 85          // 5 + C
#define NT   2048
#define CELLS (BB*AA*HH*WW)   // 393216

#define CONF_THREADS 256
#define CONF_BLOCKS  768      // 768*256*2 = 393216 cells
#define CONF_CPT     2

// Epoch-tagged claim words: g_mask[c] = (epoch<<3)|bits; bit0=obj, bit1=kz,
// bit2=cross. Stale-epoch words read as empty -> no reset pass ever.
// Accumulators reset by k_final each call => replay-deterministic output.
__device__ int      g_mask[CELLS];
__device__ unsigned g_epoch;
__device__ double g_acc[4];                  // 0:conf 1:xywh 2:cls
__device__ unsigned long long g_cnt;         // packed n_obj/n_kz/n_cross

__device__ __forceinline__ float softplusf(float x) {
    return fmaxf(x, 0.0f) + log1pf(expf(-fabsf(x)));
}
__device__ __forceinline__ float warp_sum(float v) {
    #pragma unroll
    for (int o = 16; o > 0; o >>= 1) v += __shfl_down_sync(0xFFFFFFFFu, v, o);
    return v;
}
__device__ __forceinline__ int warp_sumi(int v) {
    #pragma unroll
    for (int o = 16; o > 0; o >>= 1) v += __shfl_down_sync(0xFFFFFFFFu, v, o);
    return v;
}

// Claim `bit` on cell c for this epoch; returns bits present BEFORE the claim.
__device__ __forceinline__ int claim_bits(int c, int bit, unsigned epoch) {
    int* addr = &g_mask[c];
    const unsigned tag = epoch << 3;
    unsigned old = (unsigned)*addr;
    while (true) {
        const unsigned cur = ((old >> 3) == epoch) ? (old & 7u) : 0u;
        const unsigned nv  = tag | cur | (unsigned)bit;
        const unsigned got = (unsigned)atomicCAS(addr, (int)old, (int)nv);
        if (got == old) return (int)cur;
        old = got;
    }
}

// ---------------------------------------------------------------------------
// Kernel T: one WARP per target (structure = champion k_targets), but mask
// writes become epoch-claims with order-independent conf corrections, so it
// can run CONCURRENTLY with k_conf.
// ---------------------------------------------------------------------------
__global__ void k_targets(const float* __restrict__ pred,
                          const float* __restrict__ target,
                          const float* __restrict__ anchors)
{
    const int tid  = threadIdx.x;
    const int lane = tid & 31;
    const int wrp  = tid >> 5;
    const int n    = blockIdx.x * 8 + wrp;
    const unsigned epoch = g_epoch;

    const float* t = target + n * 6;
    const float tb = __ldg(t + 0);
    const float tl = __ldg(t + 1);
    const float tx = __ldg(t + 2) * (float)HH;
    const float ty = __ldg(t + 3) * (float)HH;
    const float tw = __ldg(t + 4) * (float)HH;
    const float th = __ldg(t + 5) * (float)HH;

    const int b   = (int)tb;
    const int lab = (int)tl;
    const int wi  = (int)tw;   // grid indices come from WH in the reference
    const int hi  = (int)th;

    float ious[AA];
    float best = -1.0f;
    int   besta = 0;
    #pragma unroll
    for (int a = 0; a < AA; ++a) {
        const float aw = __ldg(anchors + 2*a), ah = __ldg(anchors + 2*a + 1);
        const float inter = fminf(aw, tw) * fminf(ah, th);
        const float iou = inter / (aw*ah + tw*th - inter);
        ious[a] = iou;
        if (iou > best) { best = iou; besta = a; }
    }

    const int cell_best = ((b*AA + besta)*HH + hi)*WW + wi;
    const float* prow = pred + (long long)cell_best * PRED_LAST;

    // claims + conf corrections (lanes 0-2: kz per anchor, lane 3: obj+xywh)
    float conf = 0.0f, xywh = 0.0f;
    int n_obj = 0, n_kz = 0, n_cross = 0;

    if (lane < 3) {
        if (ious[lane] > 0.5f) {
            const int c = ((b*AA + lane)*HH + hi)*WW + wi;
            const float pc = __ldg(pred + c * PRED_LAST + 4);
            const int prev = claim_bits(c, 2, epoch);
            if (!(prev & 2)) {
                conf -= softplusf(pc);
                n_kz = 1;
                if (prev & 1) {
                    const int p2 = claim_bits(c, 4, epoch);
                    if (!(p2 & 4)) { conf += softplusf(pc); n_cross = 1; }
                }
            }
        }
    } else if (lane == 3) {
        const int c = cell_best;
        const float pc = __ldg(prow + 4);
        const int prev = claim_bits(c, 1, epoch);
        if (!(prev & 1)) {
            conf -= pc;            // base counted sp(pc); obj term = sp - pc
            n_obj = 1;
            if (prev & 2) {
                const int p2 = claim_bits(c, 4, epoch);
                if (!(p2 & 4)) { conf += softplusf(pc); n_cross = 1; }
            }
        }
        const float fx = tx - floorf(tx);
        const float fy = ty - floorf(ty);
        const float lw = logf(tw / __ldg(anchors + 2*besta));
        const float lh = logf(th / __ldg(anchors + 2*besta + 1));
        const float d0 = prow[0] - fx, d1 = prow[1] - fy;
        const float d2 = prow[2] - lw, d3 = prow[3] - lh;
        xywh = d0*d0 + d1*d1 + d2*d2 + d3*d3;
    }

    // cls BCE over one-hot: 80 channels -> lanes handle c, c+32, c+64
    const float* pcls = prow + 5;
    const float x0 = __ldg(pcls + lane);
    const float x1 = __ldg(pcls + lane + 32);
    const float x2 = (lane < 16) ? __ldg(pcls + lane + 64) : 0.0f;

    float s = softplusf(x0) + softplusf(x1);
    if (lane < 16) s += softplusf(x2);
    if (lab < 32)      { if (lane == lab)      s -= x0; }
    else if (lab < 64) { if (lane == lab - 32) s -= x1; }
    else               { if (lane == lab - 64) s -= x2; }

    s    = warp_sum(s);
    conf = warp_sum(conf);
    xywh = warp_sum(xywh);
    int cnt = warp_sumi((n_obj << 20) | (n_kz << 10) | n_cross);

    __shared__ float scl[8], sxy[8], scf[8];
    __shared__ int   sct[8];
    if (lane == 0) { scl[wrp] = s; sxy[wrp] = xywh; scf[wrp] = conf; sct[wrp] = cnt; }
    __syncthreads();
    if (tid == 0) {
        float cs = 0.0f, xs = 0.0f, cf = 0.0f; int ci = 0;
        #pragma unroll
        for (int w = 0; w < 8; ++w) { cs += scl[w]; xs += sxy[w]; cf += scf[w]; ci += sct[w]; }
        atomicAdd(&g_acc[2], (double)cs);
        atomicAdd(&g_acc[1], (double)xs);
        atomicAdd(&g_acc[0], (double)cf);
        // per-block fields <= 8*... safe; widen before packing to 64-bit
        const unsigned long long p =
            ((unsigned long long)((ci >> 20) & 0x3FF) << 40) |
            ((unsigned long long)((ci >> 10) & 0x3FF) << 20) |
             (unsigned long long)( ci        & 0x3FF);
        atomicAdd(&g_cnt, p);
    }
}

// ---------------------------------------------------------------------------
// Kernel C: PURE conf base stream — no mask access at all. Runs concurrently
// with k_targets on a parallel stream.
// ---------------------------------------------------------------------------
__global__ void __launch_bounds__(CONF_THREADS) k_conf(const float* __restrict__ pred)
{
    const int base   = blockIdx.x * CONF_THREADS + threadIdx.x;
    const int stride = CONF_BLOCKS * CONF_THREADS;

    float pc[CONF_CPT];
    #pragma unroll
    for (int k = 0; k < CONF_CPT; ++k)
        pc[k] = __ldg(pred + (base + k * stride) * PRED_LAST + 4);

    float conf = 0.0f;
    #pragma unroll
    for (int k = 0; k < CONF_CPT; ++k) conf += softplusf(pc[k]);

    conf = warp_sum(conf);
    __shared__ float sc[8];
    const int lane = threadIdx.x & 31, wrp = threadIdx.x >> 5;
    if (lane == 0) sc[wrp] = conf;
    __syncthreads();
    if (threadIdx.x == 0) {
        float cs = 0.0f;
        #pragma unroll
        for (int w = 0; w < 8; ++w) cs += sc[w];
        atomicAdd(&g_acc[0], (double)cs);
    }
}

// ---------------------------------------------------------------------------
// Kernel F: finalize + reset accumulators + bump epoch.
// ---------------------------------------------------------------------------
__global__ void k_final(float* __restrict__ out)
{
    const double conf = g_acc[0];
    const double xywh = g_acc[1];
    const double cls  = g_acc[2];
    const unsigned long long n = g_cnt;
    const double nobj   = (double)((n >> 40) & 0xFFFFF);
    const double nkz    = (double)((n >> 20) & 0xFFFFF);
    const double ncross = (double)( n        & 0xFFFFF);
    const double n_noobj = (double)CELLS - nobj - nkz + ncross;

    out[0] = (float)(xywh / ((double)NT * 4.0)
                   + conf / (nobj + n_noobj)
                   + cls  / ((double)NT * (double)CC));

    g_acc[0] = 0.0; g_acc[1] = 0.0; g_acc[2] = 0.0;
    g_cnt = 0ull;
    g_epoch = g_epoch + 1;   // fresh claim epoch next call (no mask reset)
}

// ---------------------------------------------------------------------------
// Host: fork/join two streams inside graph capture so k_conf (BW-bound) and
// k_targets (latency-bound) overlap. Stream/events created on first call
// (the correctness run, before capture); identical launch pattern every call.
// ---------------------------------------------------------------------------
static cudaStream_t g_side = nullptr;
static cudaEvent_t  g_evF = nullptr, g_evJ = nullptr;

extern "C" void kernel_launch(void* const* d_in, const int* in_sizes, int n_in,
                              void* d_out, int out_size)
{
    const float* pred    = (const float*)d_in[0];
    const float* target  = (const float*)d_in[1];
    const float* anchors = (const float*)d_in[2];
    float* out = (float*)d_out;

    if (g_side == nullptr) {
        cudaStreamCreateWithFlags(&g_side, cudaStreamNonBlocking);
        cudaEventCreateWithFlags(&g_evF, cudaEventDisableTiming);
        cudaEventCreateWithFlags(&g_evJ, cudaEventDisableTiming);
    }

    // fork: side stream joins the (possibly capturing) default work stream
    cudaEventRecord(g_evF, 0);
    cudaStreamWaitEvent(g_side, g_evF, 0);

    k_conf<<<CONF_BLOCKS, CONF_THREADS>>>(pred);            // main stream (big, BW-bound)
    k_targets<<<NT / 8, 256, 0, g_side>>>(pred, target, anchors);  // side stream

    // join
    cudaEventRecord(g_evJ, g_side);
    cudaStreamWaitEvent(0, g_evJ, 0);

    k_final<<<1, 1>>>(out);
}

// round 11
// speedup vs baseline: 1.2527x; 1.2527x over previous
#include <cuda_runtime.h>
#include <math.h>

// Problem constants (fixed by setup_inputs)
#define BB   32
#define AA   3
#define HH   64
#define WW   64
#define CC   80
#define PRED_LAST 85          // 5 + C
#define NT   2048
#define CELLS (BB*AA*HH*WW)   // 393216

#define CONF_THREADS 256
#define CONF_BLOCKS  192      // 49152 threads * 8 cells = 393216

// Scratch: zero-initialized device globals. Each kernel that consumes them
// resets them in the same pass (graph-replay safe, deterministic).
__device__ unsigned char g_obj[CELLS];       // obj mask
__device__ unsigned char g_kz[CELLS];        // "keep product is zero" sticky flag
__device__ double g_acc[4];                  // 0:conf 1:xywh 2:cls
__device__ unsigned long long g_cnt;         // (n_obj<<32) | n_noobj

__device__ __forceinline__ float softplusf(float x) {
    return fmaxf(x, 0.0f) + log1pf(expf(-fabsf(x)));
}

__device__ __forceinline__ float warp_sum(float v) {
    #pragma unroll
    for (int o = 16; o > 0; o >>= 1) v += __shfl_down_sync(0xFFFFFFFFu, v, o);
    return v;
}

// ---------------------------------------------------------------------------
// Kernel 1: one WARP per target; 8 targets per 256-thread block.  (R2-exact)
// ---------------------------------------------------------------------------
__global__ void k_targets(const float* __restrict__ pred,
                          const float* __restrict__ target,
                          const float* __restrict__ anchors)
{
    const int tid  = threadIdx.x;
    const int lane = tid & 31;
    const int wrp  = tid >> 5;
    const int n    = blockIdx.x * 8 + wrp;

    const float* t = target + n * 6;
    const float tb = __ldg(t + 0);
    const float tl = __ldg(t + 1);
    const float tx = __ldg(t + 2) * (float)HH;
    const float ty = __ldg(t + 3) * (float)HH;
    const float tw = __ldg(t + 4) * (float)HH;
    const float th = __ldg(t + 5) * (float)HH;

    const int b   = (int)tb;
    const int lab = (int)tl;
    const int wi  = (int)tw;   // grid indices come from WH in the reference
    const int hi  = (int)th;

    // IoU vs 3 anchors; argmax with first-max tie-break (strict >)
    float ious[AA];
    float best = -1.0f;
    int   besta = 0;
    #pragma unroll
    for (int a = 0; a < AA; ++a) {
        const float aw = __ldg(anchors + 2*a), ah = __ldg(anchors + 2*a + 1);
        const float inter = fminf(aw, tw) * fminf(ah, th);
        const float iou = inter / (aw*ah + tw*th - inter);
        ious[a] = iou;
        if (iou > best) { best = iou; besta = a; }
    }

    const int cell_best = ((b*AA + besta)*HH + hi)*WW + wi;
    const float* prow = pred + (long long)cell_best * PRED_LAST;

    float xywh = 0.0f;
    if (lane == 0) {
        #pragma unroll
        for (int a = 0; a < AA; ++a) {
            if (ious[a] > 0.5f) g_kz[((b*AA + a)*HH + hi)*WW + wi] = 1;
        }
        g_obj[cell_best] = 1;

        const float fx = tx - floorf(tx);
        const float fy = ty - floorf(ty);
        const float lw = logf(tw / __ldg(anchors + 2*besta));
        const float lh = logf(th / __ldg(anchors + 2*besta + 1));
        const float d0 = prow[0] - fx, d1 = prow[1] - fy;
        const float d2 = prow[2] - lw, d3 = prow[3] - lh;
        xywh = d0*d0 + d1*d1 + d2*d2 + d3*d3;
    }

    // cls BCE over one-hot: 80 channels -> lanes handle c, c+32, c+64
    const float* pcls = prow + 5;
    const float x0 = __ldg(pcls + lane);
    const float x1 = __ldg(pcls + lane + 32);
    const float x2 = (lane < 16) ? __ldg(pcls + lane + 64) : 0.0f;

    float s = softplusf(x0) + softplusf(x1);
    if (lane < 16) s += softplusf(x2);
    if (lane == (lab & 31) && (lab >> 5) == 0) s -= x0;
    if (lane == (lab - 32)) s -= x1;
    if (lane == (lab - 64)) s -= x2;

    s = warp_sum(s);   // lane 0 holds warp cls sum

    __shared__ float scl[8];
    __shared__ float sxy[8];
    if (lane == 0) { scl[wrp] = s; sxy[wrp] = xywh; }
    __syncthreads();
    if (tid == 0) {
        float cs = 0.0f, xs = 0.0f;
        #pragma unroll
        for (int w = 0; w < 8; ++w) { cs += scl[w]; xs += sxy[w]; }
        atomicAdd(&g_acc[2], (double)cs);
        atomicAdd(&g_acc[1], (double)xs);
    }
}

// ---------------------------------------------------------------------------
// Kernel 2: full-grid conf term, 8 cells per thread. ONLY change vs the
// 12.8us champion: pred loads use __ldcs (ld.global.cs, streaming/evict-
// first) to suppress 32B->128B sector promotion on the DRAM fill, cutting
// DRAM traffic from ~50MB to ~13MB per pass.
// ---------------------------------------------------------------------------
__global__ void __launch_bounds__(CONF_THREADS) k_conf(const float* __restrict__ pred)
{
    const int base   = blockIdx.x * CONF_THREADS + threadIdx.x;
    const int stride = CONF_BLOCKS * CONF_THREADS;   // 49152

    float pc[8];
    unsigned char o[8], kz[8];
    #pragma unroll
    for (int k = 0; k < 8; ++k) {
        const int c = base + k * stride;
        pc[k] = __ldcs(pred + c * PRED_LAST + 4);   // streaming hint
    }
    #pragma unroll
    for (int k = 0; k < 8; ++k) {
        const int c = base + k * stride;
        o[k]  = g_obj[c];
        kz[k] = g_kz[c];
    }

    float conf = 0.0f;
    int n_o = 0, n_n = 0;
    #pragma unroll
    for (int k = 0; k < 8; ++k) {
        const int c = base + k * stride;
        if (o[k] | kz[k]) { g_obj[c] = 0; g_kz[c] = 0; }   // reset touched cells
        const float sp = softplusf(pc[k]);
        if (o[k])        { conf += sp - pc[k]; n_o++; }     // bce(pc, 1)
        else if (!kz[k]) { conf += sp;         n_n++; }     // bce(pc, 0)
    }

    // block reduction: warp shuffle -> smem -> one atomic pair per block
    conf = warp_sum(conf);
    int cnt = (n_o << 16) | n_n;
    #pragma unroll
    for (int off = 16; off > 0; off >>= 1) cnt += __shfl_down_sync(0xFFFFFFFFu, cnt, off);

    __shared__ float sc[8];
    __shared__ int   si[8];
    const int lane = threadIdx.x & 31, wrp = threadIdx.x >> 5;
    if (lane == 0) { sc[wrp] = conf; si[wrp] = cnt; }
    __syncthreads();
    if (threadIdx.x == 0) {
        float cs = 0.0f; int ci = 0;
        #pragma unroll
        for (int w = 0; w < 8; ++w) { cs += sc[w]; ci += si[w]; }
        atomicAdd(&g_acc[0], (double)cs);
        const unsigned long long packed =
            ((unsigned long long)(unsigned)(ci >> 16) << 32) |
            (unsigned long long)(unsigned)(ci & 0xFFFF);
        atomicAdd(&g_cnt, packed);
    }
}

// ---------------------------------------------------------------------------
// Kernel 3: finalize + reset accumulators for the next replay.  (R2-exact)
// ---------------------------------------------------------------------------
__global__ void k_final(float* __restrict__ out)
{
    const double conf = g_acc[0];
    const double xywh = g_acc[1];
    const double cls  = g_acc[2];
    const unsigned long long cnt = g_cnt;
    const double n_obj   = (double)(cnt >> 32);
    const double n_noobj = (double)(cnt & 0xFFFFFFFFull);

    const double loss = xywh / ((double)NT * 4.0)
                      + conf / (n_obj + n_noobj)
                      + cls  / ((double)NT * (double)CC);
    out[0] = (float)loss;

    g_acc[0] = 0.0; g_acc[1] = 0.0; g_acc[2] = 0.0;
    g_cnt = 0ull;
}

extern "C" void kernel_launch(void* const* d_in, const int* in_sizes, int n_in,
                              void* d_out, int out_size)
{
    const float* pred    = (const float*)d_in[0];
    const float* target  = (const float*)d_in[1];
    const float* anchors = (const float*)d_in[2];
    float* out = (float*)d_out;

    k_targets<<<NT / 8, 256>>>(pred, target, anchors);
    k_conf<<<CONF_BLOCKS, CONF_THREADS>>>(pred);
    k_final<<<1, 1>>>(out);
}